// round 17
// baseline (speedup 1.0000x reference)
#include <cuda_runtime.h>
#include <cuda_fp16.h>
#include <cstdint>

#define T_STEPS 1024
#define A_DIM   64
#define H_DIM   2048
#define H3      (3 * H_DIM)
#define NBLK    128
#define NTHR    1024           // 32 warps: split-K, 2 warps per output element
#define JPB     16             // outputs per CTA
// sv(8KB) + fc1s(64KB) + fc2s(64KB) + part(3*32 fp32)
#define SMEM_BYTES (8192 + 2 * JPB * H_DIM * 2 + 384)

// ---------------- scratch (static device allocs: allowed) ----------------
__device__ float  g_GI[(size_t)T_STEPS * H3];       // 25.2 MB
__device__ float  g_S [(size_t)T_STEPS * H_DIM];    //  8.0 MB
__device__ __half g_Whh[(size_t)H3 * H_DIM];        // 25.2 MB fp16 copy of W_hh
__device__ float  g_s0[H_DIM];
__device__ float  g_s1[H_DIM];
__device__ unsigned g_count;                        // monotonic barrier counter

// ---------------- helpers ----------------
__device__ __forceinline__ float sigmoidf_(float x) { return 1.0f / (1.0f + expf(-x)); }
__device__ __forceinline__ float eluf_(float x)     { return x > 0.0f ? x : expm1f(x); }
__device__ __forceinline__ float softplusf_(float x){ return fmaxf(x, 0.0f) + log1pf(expf(-fabsf(x))); }

__device__ __forceinline__ float warp_sum(float v) {
    #pragma unroll
    for (int o = 16; o > 0; o >>= 1) v += __shfl_xor_sync(0xFFFFFFFFu, v, o);
    return v;
}

// 8-halfs fp16 dot against 8 fp32 values (two float4), fp32 accumulate.
__device__ __forceinline__ float dot8(uint4 w, float4 h0, float4 h1) {
    float2 p0 = __half22float2(*(__half2*)&w.x);
    float2 p1 = __half22float2(*(__half2*)&w.y);
    float2 p2 = __half22float2(*(__half2*)&w.z);
    float2 p3 = __half22float2(*(__half2*)&w.w);
    return p0.x*h0.x + p0.y*h0.y + p1.x*h0.z + p1.y*h0.w
         + p2.x*h1.x + p2.y*h1.y + p3.x*h1.z + p3.y*h1.w;
}

// Single-counter monotonic grid barrier with backoff. Release condition:
// total arrivals >= NBLK*epoch (induction: arrival k+1 requires passing
// barrier k). Correctness empirically validated in R13/R14.
__device__ __forceinline__ void grid_barrier(unsigned target) {
    __syncthreads();
    if (threadIdx.x == 0) {
        __threadfence();
        atomicAdd(&g_count, 1u);
        unsigned v;
        for (;;) {
            asm volatile("ld.global.cv.u32 %0, [%1];" : "=r"(v) : "l"(&g_count));
            if (v >= target) break;
            __nanosleep(64);           // bound poll traffic on the hot line
        }
        __threadfence();
    }
    __syncthreads();
}

// ---------------- kernel 0a: reset barrier state (graph-replay safety) ----
__global__ void reset_kernel() {
    if (threadIdx.x == 0) g_count = 0u;
}

// ---------------- kernel 0b: W_hh fp32 -> fp16 ----------------
__global__ void conv_whh_kernel(const float* __restrict__ W_hh) {
    size_t i = ((size_t)blockIdx.x * blockDim.x + threadIdx.x);   // float4 index
    float4 v = __ldg((const float4*)W_hh + i);
    __half2 h0 = __floats2half2_rn(v.x, v.y);
    __half2 h1 = __floats2half2_rn(v.z, v.w);
    uint2 o;
    o.x = *(unsigned*)&h0;
    o.y = *(unsigned*)&h1;
    ((uint2*)g_Whh)[i] = o;
}

// ---------------- kernel 1: GI = actions @ W_ih^T + b_ih ----------------
#define GI_TB 64
__global__ void __launch_bounds__(256) gi_kernel(
    const float* __restrict__ actions,
    const float* __restrict__ W_ih,
    const float* __restrict__ b_ih)
{
    __shared__ float act[GI_TB][A_DIM];    // 16 KB
    const int t0 = blockIdx.y * GI_TB;
    const int g  = blockIdx.x * 256 + threadIdx.x;

    for (int idx = threadIdx.x; idx < GI_TB * A_DIM / 4; idx += 256)
        ((float4*)&act[0][0])[idx] = ((const float4*)(actions + (size_t)t0 * A_DIM))[idx];
    __syncthreads();

    const float4* w = (const float4*)(W_ih + (size_t)g * A_DIM);
    float4 wreg[A_DIM / 4];
    #pragma unroll
    for (int i = 0; i < A_DIM / 4; i++) wreg[i] = __ldg(w + i);
    const float b = __ldg(b_ih + g);

    for (int tt = 0; tt < GI_TB; tt++) {
        float acc = b;
        #pragma unroll
        for (int i = 0; i < A_DIM / 4; i++) {
            float4 a = ((const float4*)act[tt])[i];
            acc += wreg[i].x*a.x + wreg[i].y*a.y + wreg[i].z*a.z + wreg[i].w*a.w;
        }
        g_GI[(size_t)(t0 + tt) * H3 + g] = acc;
    }
}

// ---------------- kernel 2: persistent sequential scan ----------------
// Split-K, gate-sequential: 32 warps/CTA, output j owned by warp pair
// (wj, wj+16); each warp dots a 1024-element K-half. Phase 1 walks the three
// gate rows SEQUENTIALLY so the live register set stays under the 64-reg cap
// at 1024 threads (R13's spill bug). Partials combine through SMEM.
__global__ void __launch_bounds__(NTHR, 1) scan_kernel(
    const float* __restrict__ state,
    const float* __restrict__ b_hh,
    const float* __restrict__ fc1_w, const float* __restrict__ fc1_b,
    const float* __restrict__ fc2_w, const float* __restrict__ fc2_b)
{
    extern __shared__ char smem[];
    float*  sv   = (float*)smem;                       // 2048 fp32
    __half* fc1s = (__half*)(smem + 8192);             // JPB x 2048 half
    __half* fc2s = fc1s + JPB * H_DIM;                 // JPB x 2048 half
    float*  part = (float*)(fc2s + JPB * H_DIM);       // [3][32] partials

    const int tid  = threadIdx.x;
    const int warp = tid >> 5;
    const int lane = tid & 31;
    const int wj   = warp & 15;                        // output slot within CTA
    const int half = warp >> 4;                        // which K-half this warp does
    const int j    = blockIdx.x * JPB + wj;            // output element 0..2047
    const bool combiner = (warp < 16) && (lane == 0);

    // ---- prologue: convert this CTA's fc rows to fp16 in SMEM ----
    {
        const int jbase = blockIdx.x * JPB;
        for (int idx = tid; idx < JPB * H_DIM; idx += NTHR) {
            int r = idx >> 11, c = idx & (H_DIM - 1);
            fc1s[idx] = __float2half_rn(fc1_w[(size_t)(jbase + r) * H_DIM + c]);
            fc2s[idx] = __float2half_rn(fc2_w[(size_t)(jbase + r) * H_DIM + c]);
        }
    }

    // uint4 row bases (per-gate row picked inside the gate loop)
    const uint4* w1 = (const uint4*)(fc1s + wj * H_DIM) + half * 128;
    const uint4* w2 = (const uint4*)(fc2s + wj * H_DIM) + half * 128;

    const float bh_r = __ldg(b_hh + j);
    const float bh_z = __ldg(b_hh + H_DIM + j);
    const float bh_n = __ldg(b_hh + 2 * H_DIM + j);
    const float b1   = __ldg(fc1_b + j);
    const float b2   = __ldg(fc2_b + j);

    const int svbase = half * 256;                     // float4 offset of K-half

    __syncthreads();   // fc SMEM ready (intra-CTA only)

    unsigned target = 0;
    for (int t = 0; t < T_STEPS; t++) {
        // ============ phase 1: GRU cell ============
        const float4* prev4 = (t == 0) ? (const float4*)state
                                       : (const float4*)(g_S + (size_t)(t - 1) * H_DIM);
        if (tid < H_DIM / 4)
            ((float4*)sv)[tid] = __ldcg(prev4 + tid);
        float gir = 0.f, giz = 0.f, gin = 0.f;
        if (combiner) {
            const float* gi = g_GI + (size_t)t * H3;
            gir = __ldg(gi + j);
            giz = __ldg(gi + H_DIM + j);
            gin = __ldg(gi + 2 * H_DIM + j);
        }
        __syncthreads();

        // three gate rows, sequentially (small live set -> no spills @64reg)
        #pragma unroll
        for (int g = 0; g < 3; g++) {
            const uint4* wg = (const uint4*)(g_Whh + (size_t)(g * H_DIM + j) * H_DIM)
                              + half * 128;
            float a = 0.f;
            #pragma unroll 2
            for (int ii = 0; ii < 4; ii++) {
                int i = lane + ii * 32;                // uint4 idx within K-half
                uint4 w = __ldg(wg + i);
                float4 h0 = ((const float4*)sv)[svbase + 2 * i];
                float4 h1 = ((const float4*)sv)[svbase + 2 * i + 1];
                a += dot8(w, h0, h1);
            }
            a = warp_sum(a);
            if (lane == 0) part[g * 32 + warp] = a;
        }
        __syncthreads();

        if (combiner) {
            float arT = part[wj]      + part[wj + 16];
            float azT = part[32 + wj] + part[32 + wj + 16];
            float anT = part[64 + wj] + part[64 + wj + 16];
            float r = sigmoidf_(gir + arT + bh_r);
            float z = sigmoidf_(giz + azT + bh_z);
            float n = tanhf   (gin + r * (anT + bh_n));
            float hnew = (1.0f - z) * n + z * sv[j];
            __stcg(&g_s0[j], eluf_(hnew));
        }
        target += NBLK; grid_barrier(target);

        // ============ phase 2: s1 = elu(s0 @ fc1^T + b1) ============
        if (tid < H_DIM / 4)
            ((float4*)sv)[tid] = __ldcg((const float4*)g_s0 + tid);
        __syncthreads();
        float acc1 = 0.f;
        #pragma unroll
        for (int ii = 0; ii < 4; ii++) {
            int i = lane + ii * 32;
            float4 h0 = ((const float4*)sv)[svbase + 2 * i];
            float4 h1 = ((const float4*)sv)[svbase + 2 * i + 1];
            acc1 += dot8(w1[i], h0, h1);
        }
        acc1 = warp_sum(acc1);
        if (lane == 0) part[warp] = acc1;
        __syncthreads();
        if (combiner)
            __stcg(&g_s1[j], eluf_(part[wj] + part[wj + 16] + b1));
        target += NBLK; grid_barrier(target);

        // ============ phase 3: s2 = elu(s1 @ fc2^T + b2) ============
        if (tid < H_DIM / 4)
            ((float4*)sv)[tid] = __ldcg((const float4*)g_s1 + tid);
        __syncthreads();
        float acc2 = 0.f;
        #pragma unroll
        for (int ii = 0; ii < 4; ii++) {
            int i = lane + ii * 32;
            float4 h0 = ((const float4*)sv)[svbase + 2 * i];
            float4 h1 = ((const float4*)sv)[svbase + 2 * i + 1];
            acc2 += dot8(w2[i], h0, h1);
        }
        acc2 = warp_sum(acc2);
        if (lane == 0) part[warp] = acc2;
        __syncthreads();
        if (combiner)
            __stcg(&g_S[(size_t)t * H_DIM + j], eluf_(part[wj] + part[wj + 16] + b2));
        target += NBLK; grid_barrier(target);
    }
}

// ---------------- kernel 3: heads — out = S @ W^T + b (softplus for std) ----
__global__ void __launch_bounds__(256) head_gemm(
    const float* __restrict__ mean_w, const float* __restrict__ mean_b,
    const float* __restrict__ std_w,  const float* __restrict__ std_b,
    float* __restrict__ out)
{
    const float* Wmat = blockIdx.z ? std_w : mean_w;
    const float* bias = blockIdx.z ? std_b : mean_b;
    const int m0 = blockIdx.y * 128;
    const int n0 = blockIdx.x * 128;

    __shared__ float As[8][128];
    __shared__ float Bs[8][128];

    const int tid  = threadIdx.x;
    const int lrow = tid >> 1;
    const int lcol = (tid & 1) * 4;
    const int tx   = tid & 15;
    const int ty   = tid >> 4;

    float acc[8][8];
    #pragma unroll
    for (int i = 0; i < 8; i++)
        #pragma unroll
        for (int jj = 0; jj < 8; jj++) acc[i][jj] = 0.f;

    const float* aptr = g_S  + (size_t)(m0 + lrow) * H_DIM + lcol;
    const float* bptr = Wmat + (size_t)(n0 + lrow) * H_DIM + lcol;

    for (int k0 = 0; k0 < H_DIM; k0 += 8) {
        float4 a4 = *(const float4*)(aptr + k0);
        float4 b4 = *(const float4*)(bptr + k0);
        __syncthreads();
        As[lcol+0][lrow] = a4.x; As[lcol+1][lrow] = a4.y;
        As[lcol+2][lrow] = a4.z; As[lcol+3][lrow] = a4.w;
        Bs[lcol+0][lrow] = b4.x; Bs[lcol+1][lrow] = b4.y;
        Bs[lcol+2][lrow] = b4.z; Bs[lcol+3][lrow] = b4.w;
        __syncthreads();
        #pragma unroll
        for (int kk = 0; kk < 8; kk++) {
            float a[8], b[8];
            *(float4*)&a[0] = *(const float4*)&As[kk][ty * 4];
            *(float4*)&a[4] = *(const float4*)&As[kk][ty * 4 + 64];
            *(float4*)&b[0] = *(const float4*)&Bs[kk][tx * 4];
            *(float4*)&b[4] = *(const float4*)&Bs[kk][tx * 4 + 64];
            #pragma unroll
            for (int i = 0; i < 8; i++)
                #pragma unroll
                for (int jj = 0; jj < 8; jj++)
                    acc[i][jj] += a[i] * b[jj];
        }
    }

    const size_t zoff = (size_t)blockIdx.z * T_STEPS * H_DIM;
    #pragma unroll
    for (int i = 0; i < 8; i++) {
        int m = m0 + ty * 4 + (i & 3) + (i >> 2) * 64;
        #pragma unroll
        for (int jj = 0; jj < 8; jj++) {
            int n = n0 + tx * 4 + (jj & 3) + (jj >> 2) * 64;
            float v = acc[i][jj] + bias[n];
            if (blockIdx.z) v = softplusf_(v);
            out[zoff + (size_t)m * H_DIM + n] = v;
        }
    }
}

// ---------------- launch ----------------
extern "C" void kernel_launch(void* const* d_in, const int* in_sizes, int n_in,
                              void* d_out, int out_size) {
    const float* actions = (const float*)d_in[0];
    const float* state   = (const float*)d_in[1];
    const float* W_ih    = (const float*)d_in[2];
    const float* W_hh    = (const float*)d_in[3];
    const float* b_ih    = (const float*)d_in[4];
    const float* b_hh    = (const float*)d_in[5];
    const float* fc1_w   = (const float*)d_in[6];
    const float* fc1_b   = (const float*)d_in[7];
    const float* fc2_w   = (const float*)d_in[8];
    const float* fc2_b   = (const float*)d_in[9];
    const float* mean_w  = (const float*)d_in[10];
    const float* mean_b  = (const float*)d_in[11];
    const float* std_w   = (const float*)d_in[12];
    const float* std_b   = (const float*)d_in[13];
    float* out = (float*)d_out;

    static bool attr_set = false;
    if (!attr_set) {
        cudaFuncSetAttribute(scan_kernel,
                             cudaFuncAttributeMaxDynamicSharedMemorySize, SMEM_BYTES);
        attr_set = true;
    }

    reset_kernel<<<1, 32>>>();
    conv_whh_kernel<<<(H3 * H_DIM / 4) / 256, 256>>>(W_hh);
    gi_kernel<<<dim3(H3 / 256, T_STEPS / GI_TB), 256>>>(actions, W_ih, b_ih);
    scan_kernel<<<NBLK, NTHR, SMEM_BYTES>>>(state, b_hh, fc1_w, fc1_b, fc2_w, fc2_b);
    head_gemm<<<dim3(H_DIM / 128, T_STEPS / 128, 2), 256>>>(mean_w, mean_b, std_w, std_b, out);
}